// round 3
// baseline (speedup 1.0000x reference)
#include <cuda_runtime.h>
#include <cstdint>

// QuantizationLayer: out[i*4 + {0..3}] = bits (MSB-first) of round_half_even(x[i]*16 - 0.5)
// x: (32768, 512) f32 in [0,1)  ->  out: (32768, 2048) f32 of {0.0, 1.0}
//
// Streaming kernel, 8 elements per thread, blockDim-strided:
//   - every LDG.32 is a coalesced 128B/warp
//   - every STG.128 is a coalesced 512B/warp
//   - MLP = 8 independent loads in flight per thread
// __ldcs/__stcs: evict-first streaming (read-once / write-once data).

#define ELEMS_PER_THREAD 8
#define THREADS 256

__global__ void __launch_bounds__(THREADS)
quant_unpack_kernel(const float* __restrict__ x,
                    float4* __restrict__ out,
                    int n) {
    const int tile = THREADS * ELEMS_PER_THREAD;
    int base = blockIdx.x * tile + threadIdx.x;

    float v[ELEMS_PER_THREAD];

    if (base + (ELEMS_PER_THREAD - 1) * THREADS < n) {
        // Fast path: whole tile in range, no per-element guards.
#pragma unroll
        for (int k = 0; k < ELEMS_PER_THREAD; k++)
            v[k] = __ldcs(x + base + k * THREADS);

#pragma unroll
        for (int k = 0; k < ELEMS_PER_THREAD; k++) {
            // round-half-to-even (rintf = RN nearest-even), matches jnp.round.
            // x*16 exact (pow2), -0.5 exact, code in [0,15].
            int c = ((int)rintf(fmaf(v[k], 16.0f, -0.5f))) & 15;
            float4 bits;
            bits.x = (float)((c >> 3) & 1);
            bits.y = (float)((c >> 2) & 1);
            bits.z = (float)((c >> 1) & 1);
            bits.w = (float)(c & 1);
            __stcs(out + base + k * THREADS, bits);
        }
    } else {
        // Tail path (not taken for n = 16,777,216)
#pragma unroll
        for (int k = 0; k < ELEMS_PER_THREAD; k++) {
            int i = base + k * THREADS;
            if (i >= n) continue;
            float vv = __ldcs(x + i);
            int c = ((int)rintf(fmaf(vv, 16.0f, -0.5f))) & 15;
            float4 bits;
            bits.x = (float)((c >> 3) & 1);
            bits.y = (float)((c >> 2) & 1);
            bits.z = (float)((c >> 1) & 1);
            bits.w = (float)(c & 1);
            __stcs(out + i, bits);
        }
    }
}

extern "C" void kernel_launch(void* const* d_in, const int* in_sizes, int n_in,
                              void* d_out, int out_size) {
    const float* x = (const float*)d_in[0];
    float4* out = (float4*)d_out;
    int n = in_sizes[0];  // 32768*512 = 16,777,216

    const int per_block = THREADS * ELEMS_PER_THREAD;  // 2048
    int blocks = (n + per_block - 1) / per_block;      // 8192
    quant_unpack_kernel<<<blocks, THREADS>>>(x, out, n);
}